// round 8
// baseline (speedup 1.0000x reference)
#include <cuda_runtime.h>
#include <cuda_fp16.h>
#include <cstdint>

// Problem constants
#define BATCH   2
#define SEQ     2048
#define DMODEL  1024
#define NHEADS  16
#define HDIM    64
#define CEXP    92.33248261689366f   // SCALE(=64) * log2(e)
#define NELEM   (BATCH * SEQ * DMODEL)

// Scratch
__device__ __half g_WT_hi[3 * DMODEL * DMODEL];
__device__ __half g_WT_lo[3 * DMODEL * DMODEL];
__device__ __half g_Ah[3 * NELEM];
__device__ __half g_Al[3 * NELEM];
__device__ __half g_Qh[NELEM];
__device__ __half g_Ql[NELEM];
__device__ __half g_Kh[NELEM];
__device__ __half g_Kl[NELEM];
__device__ __half g_Vh[NELEM];
__device__ unsigned g_ctr_attn;
__device__ unsigned g_ctr_proj;

// ===========================================================================
// Helpers (sm_80-era PTX only)
// ===========================================================================
__device__ __forceinline__ uint32_t smem_u32(const void* p) {
    uint32_t a;
    asm("{ .reg .u64 t; cvta.to.shared.u64 t, %1; cvt.u32.u64 %0, t; }" : "=r"(a) : "l"(p));
    return a;
}
__device__ __forceinline__ void ldm_x4(uint32_t addr, uint32_t* r) {
    asm volatile("ldmatrix.sync.aligned.m8n8.x4.shared.b16 {%0,%1,%2,%3}, [%4];"
                 : "=r"(r[0]), "=r"(r[1]), "=r"(r[2]), "=r"(r[3]) : "r"(addr));
}
__device__ __forceinline__ void ldm_x4t(uint32_t addr, uint32_t* r) {
    asm volatile("ldmatrix.sync.aligned.m8n8.x4.trans.shared.b16 {%0,%1,%2,%3}, [%4];"
                 : "=r"(r[0]), "=r"(r[1]), "=r"(r[2]), "=r"(r[3]) : "r"(addr));
}
__device__ __forceinline__ void mma_f16(float* c, const uint32_t* a, uint32_t b0, uint32_t b1) {
    asm volatile("mma.sync.aligned.m16n8k16.row.col.f32.f16.f16.f32 "
                 "{%0,%1,%2,%3}, {%4,%5,%6,%7}, {%8,%9}, {%0,%1,%2,%3};"
                 : "+f"(c[0]), "+f"(c[1]), "+f"(c[2]), "+f"(c[3])
                 : "r"(a[0]), "r"(a[1]), "r"(a[2]), "r"(a[3]), "r"(b0), "r"(b1));
}
__device__ __forceinline__ uint32_t pack_h2(float p0, float p1) {
    uint32_t h;
    asm("cvt.rn.f16x2.f32 %0, %1, %2;" : "=r"(h) : "f"(p1), "f"(p0));
    return h;
}
__device__ __forceinline__ void split2h(float p0, float p1, uint32_t& hi, uint32_t& lo) {
    uint32_t h = pack_h2(p0, p1);
    float f0, f1;
    asm("{.reg .b16 a,b; mov.b32 {a,b}, %2; cvt.f32.f16 %0, a; cvt.f32.f16 %1, b;}"
        : "=f"(f0), "=f"(f1) : "r"(h));
    hi = h;
    lo = pack_h2(p0 - f0, p1 - f1);
}
__device__ __forceinline__ float ex2(float x) {
    float r;
    asm("ex2.approx.f32 %0, %1;" : "=f"(r) : "f"(x));
    return r;
}
__device__ __forceinline__ uint32_t h2ex2(uint32_t x) {
    uint32_t r;
    asm("ex2.approx.f16x2 %0, %1;" : "=r"(r) : "r"(x));
    return r;
}
__device__ __forceinline__ void cpa16(uint32_t s, const void* g) {
    asm volatile("cp.async.cg.shared.global [%0], [%1], 16;" :: "r"(s), "l"(g));
}
#define CP_COMMIT() asm volatile("cp.async.commit_group;" ::: "memory")
#define CP_WAIT0()  asm volatile("cp.async.wait_group 0;" ::: "memory")

#define ONE2 0x3C003C00u   // fp16x2 {1.0, 1.0}

// ===========================================================================
// Counter reset
// ===========================================================================
__global__ void ctr_reset() { g_ctr_attn = 0u; g_ctr_proj = 0u; }

// ===========================================================================
// W transpose + split-fp16 convert:  g_WT[z][n][k] = W_z[k][n]
// ===========================================================================
__global__ void wt_convert(const float* __restrict__ Wq, const float* __restrict__ Wk,
                           const float* __restrict__ Wv)
{
    __shared__ float tile[32][33];
    const float* W = (blockIdx.z == 0) ? Wq : (blockIdx.z == 1) ? Wk : Wv;
    const int tx = threadIdx.x, ty = threadIdx.y;
    const int k0 = blockIdx.y * 32, n0 = blockIdx.x * 32;
#pragma unroll
    for (int i = 0; i < 4; i++)
        tile[ty + i * 8][tx] = W[(size_t)(k0 + ty + i * 8) * DMODEL + n0 + tx];
    __syncthreads();
    const size_t base = (size_t)blockIdx.z * DMODEL * DMODEL;
#pragma unroll
    for (int i = 0; i < 4; i++) {
        const int n = n0 + ty + i * 8;
        const int k = k0 + tx;
        const float v = tile[tx][ty + i * 8];
        __half h = __float2half_rn(v);
        g_WT_hi[base + (size_t)n * DMODEL + k] = h;
        g_WT_lo[base + (size_t)n * DMODEL + k] = __float2half_rn(v - __half2float(h));
    }
}

// ===========================================================================
// Input split
// ===========================================================================
__global__ void in_convert(const float* __restrict__ qi, const float* __restrict__ ki,
                           const float* __restrict__ vi)
{
    const int z = blockIdx.y;
    const float* A = (z == 0) ? qi : (z == 1) ? ki : vi;
    const size_t base = (size_t)z * NELEM;
    const size_t i = ((size_t)blockIdx.x * 256 + threadIdx.x) * 4;
    float4 a = *(const float4*)(A + i);
    uint32_t h0, l0, h1, l1;
    split2h(a.x, a.y, h0, l0);
    split2h(a.z, a.w, h1, l1);
    *(uint2*)(g_Ah + base + i) = make_uint2(h0, h1);
    *(uint2*)(g_Al + base + i) = make_uint2(l0, l1);
}

// ===========================================================================
// Projection GEMM — mma reordered for distance-4 accumulator reuse +
// double-buffered B ldmatrix. Work-stealing persistent, 2-stage cp.async.
// ===========================================================================
#define PSTG 40960
#define PROJ_SMEM (2 * PSTG)
#define PROJ_GRID 296
#define PROJ_UNITS 768

__global__ __launch_bounds__(256, 2) void proj_mma()
{
    extern __shared__ char smc[];
    const uint32_t sb = smem_u32(smc);
    int* su = (int*)(smc + 64);
    const int tid = threadIdx.x;
    const int lane = tid & 31;
    const int wid = tid >> 5;
    const int g = lane >> 2, t4 = lane & 3;
    const int wm = wid & 3, wn = wid >> 2;

    const uint32_t aBase = (uint32_t)(wm * 32 + (lane & 15)) * 80 + (lane >> 4) * 16;
    const uint32_t bBase = (uint32_t)(wn * 64 + (lane & 7) + ((lane >> 4) << 3)) * 80
                           + ((lane >> 3) & 1) * 16;
    const int lr = tid >> 1, lq = tid & 1;
    const uint32_t ldB = lr * 80 + lq * 32;

    while (true) {
        if (tid == 0) *su = (int)atomicAdd(&g_ctr_proj, 1u);
        __syncthreads();
        const int u = *su;
        if (u >= PROJ_UNITS) break;

        const int z = u >> 8;
        const int rem = u & 255;
        const int m0 = (rem >> 3) * 128;
        const int n0 = (rem & 7) * 128;

        __half *Ch, *Cl;
        if (z == 0)      { Ch = g_Qh; Cl = g_Ql; }
        else if (z == 1) { Ch = g_Kh; Cl = g_Kl; }
        else             { Ch = g_Vh; Cl = 0; }
        const char* AhG = (const char*)(g_Ah + (size_t)z * NELEM);
        const char* AlG = (const char*)(g_Al + (size_t)z * NELEM);
        const size_t woff = (size_t)z * DMODEL * DMODEL;
        const char* BhG = (const char*)(g_WT_hi + woff);
        const char* BlG = (const char*)(g_WT_lo + woff);
        const size_t aRowB = (size_t)(m0 + lr) * DMODEL * 2;
        const size_t bRowB = (size_t)(n0 + lr) * DMODEL * 2;

        float c[2][8][4];
#pragma unroll
        for (int mb = 0; mb < 2; mb++)
#pragma unroll
            for (int j = 0; j < 8; j++)
#pragma unroll
                for (int i = 0; i < 4; i++) c[mb][j][i] = 0.0f;

        // prologue: stage 0
#pragma unroll
        for (int j = 0; j < 2; j++) {
            cpa16(sb + ldB + j * 16,         AhG + aRowB + lq * 32 + j * 16);
            cpa16(sb + 10240 + ldB + j * 16, AlG + aRowB + lq * 32 + j * 16);
            cpa16(sb + 20480 + ldB + j * 16, BhG + bRowB + lq * 32 + j * 16);
            if (z < 2)
                cpa16(sb + 30720 + ldB + j * 16, BlG + bRowB + lq * 32 + j * 16);
        }
        CP_COMMIT();
        CP_WAIT0();
        __syncthreads();

        for (int kb = 0; kb < 32; kb++) {
            const uint32_t stg = (uint32_t)(kb & 1) * PSTG;
            if (kb + 1 < 32) {
                const uint32_t ns = sb + (uint32_t)((kb + 1) & 1) * PSTG;
                const size_t ko = (size_t)(kb + 1) * 64 + lq * 32;
#pragma unroll
                for (int j = 0; j < 2; j++) {
                    cpa16(ns + ldB + j * 16,         AhG + aRowB + ko + j * 16);
                    cpa16(ns + 10240 + ldB + j * 16, AlG + aRowB + ko + j * 16);
                    cpa16(ns + 20480 + ldB + j * 16, BhG + bRowB + ko + j * 16);
                    if (z < 2)
                        cpa16(ns + 30720 + ldB + j * 16, BlG + bRowB + ko + j * 16);
                }
                CP_COMMIT();
            }

#pragma unroll
            for (int c2 = 0; c2 < 2; c2++) {
                uint32_t ah[2][4], al[2][4];
#pragma unroll
                for (int mb = 0; mb < 2; mb++) {
                    ldm_x4(sb + stg + aBase + mb * 1280 + c2 * 32, ah[mb]);
                    ldm_x4(sb + stg + 10240 + aBase + mb * 1280 + c2 * 32, al[mb]);
                }
                // Double-buffered B frags; distance-4 accumulator rotation.
                uint32_t bb[2][4];
                ldm_x4(sb + stg + 20480 + bBase + c2 * 32, bb[0]);
#pragma unroll
                for (int jj = 0; jj < 4; jj++) {
                    if (jj < 3)
                        ldm_x4(sb + stg + 20480 + bBase + (jj + 1) * 1280 + c2 * 32,
                               bb[(jj + 1) & 1]);
                    else if (z < 2)
                        ldm_x4(sb + stg + 30720 + bBase + c2 * 32, bb[(jj + 1) & 1]);
                    const uint32_t* b = bb[jj & 1];
                    mma_f16(c[0][2 * jj],     ah[0], b[0], b[1]);
                    mma_f16(c[1][2 * jj],     ah[1], b[0], b[1]);
                    mma_f16(c[0][2 * jj + 1], ah[0], b[2], b[3]);
                    mma_f16(c[1][2 * jj + 1], ah[1], b[2], b[3]);
                    mma_f16(c[0][2 * jj],     al[0], b[0], b[1]);
                    mma_f16(c[1][2 * jj],     al[1], b[0], b[1]);
                    mma_f16(c[0][2 * jj + 1], al[0], b[2], b[3]);
                    mma_f16(c[1][2 * jj + 1], al[1], b[2], b[3]);
                }
                if (z < 2) {
#pragma unroll
                    for (int jj = 0; jj < 4; jj++) {
                        if (jj < 3)
                            ldm_x4(sb + stg + 30720 + bBase + (jj + 1) * 1280 + c2 * 32,
                                   bb[(jj + 1) & 1]);
                        const uint32_t* b = bb[jj & 1];
                        mma_f16(c[0][2 * jj],     ah[0], b[0], b[1]);
                        mma_f16(c[1][2 * jj],     ah[1], b[0], b[1]);
                        mma_f16(c[0][2 * jj + 1], ah[0], b[2], b[3]);
                        mma_f16(c[1][2 * jj + 1], ah[1], b[2], b[3]);
                    }
                }
            }
            if (kb + 1 < 32) {
                CP_WAIT0();
                __syncthreads();
            }
        }

        // epilogue
#pragma unroll
        for (int mb = 0; mb < 2; mb++) {
#pragma unroll
            for (int j = 0; j < 8; j++) {
                const int R0 = m0 + wm * 32 + mb * 16 + g;
                const int col = n0 + wn * 64 + 8 * j + 2 * t4;
                if (z < 2) {
                    uint32_t hi, lo;
                    split2h(c[mb][j][0], c[mb][j][1], hi, lo);
                    *(uint32_t*)(Ch + (size_t)R0 * DMODEL + col) = hi;
                    *(uint32_t*)(Cl + (size_t)R0 * DMODEL + col) = lo;
                    split2h(c[mb][j][2], c[mb][j][3], hi, lo);
                    *(uint32_t*)(Ch + (size_t)(R0 + 8) * DMODEL + col) = hi;
                    *(uint32_t*)(Cl + (size_t)(R0 + 8) * DMODEL + col) = lo;
                } else {
                    *(uint32_t*)(Ch + (size_t)R0 * DMODEL + col) =
                        pack_h2(c[mb][j][0], c[mb][j][1]);
                    *(uint32_t*)(Ch + (size_t)(R0 + 8) * DMODEL + col) =
                        pack_h2(c[mb][j][2], c[mb][j][3]);
                }
            }
        }
    }
}

// ===========================================================================
// Flash attention — S-loop reordered in jj-pairs (distance-4), PV loop with
// front-loaded V ldmatrix. 128-thread CTAs, 3/SM, work-stealing persistent.
// ===========================================================================
#define A_QL   9216
#define A_STG0 18432
#define A_STGSZ 27648
#define ATTN_SMEM 73728
#define ATTN_GRID 444
#define ATTN_UNITS 1024

__global__ __launch_bounds__(128, 3) void attn_mma(float* __restrict__ out)
{
    extern __shared__ char smc[];
    const uint32_t sb = smem_u32(smc);
    int* su = (int*)(smc + 128);
    const int tid = threadIdx.x;
    const int lane = tid & 31;
    const int w = tid >> 5;
    const int g = lane >> 2, t4 = lane & 3;
    const int lr = tid >> 1, lq = tid & 1;
    const uint32_t ldKV = lr * 144 + lq * 64;

    const uint32_t qBase = (uint32_t)(16 * w + (lane & 15)) * 144 + (lane >> 4) * 16;
    const uint32_t kBase = (uint32_t)((lane & 7) + ((lane >> 4) << 3)) * 144
                           + ((lane >> 3) & 1) * 16;
    const uint32_t vBase = (uint32_t)((lane & 7) + (((lane >> 3) & 1) << 3)) * 144
                           + (lane >> 4) * 16;

    while (true) {
        if (tid == 0) *su = (int)atomicAdd(&g_ctr_attn, 1u);
        __syncthreads();
        const int u = *su;
        if (u >= ATTN_UNITS) break;

        const int b = u >> 9;
        const int h = (u >> 5) & 15;
        const int q0 = (u & 31) * 64;
        const int hoff = h * HDIM;

        // prologue: Q (2 planes) + KV tile 0
        {
            const size_t gQ = ((size_t)(b * SEQ + q0 + lr) * DMODEL + hoff) * 2 + lq * 64;
            const size_t gB = ((size_t)(b * SEQ + lr) * DMODEL + hoff) * 2 + lq * 64;
            const uint32_t dQ = sb + ldKV;
            const uint32_t dKV = sb + A_STG0 + ldKV;
#pragma unroll
            for (int i = 0; i < 4; i++) {
                cpa16(dQ + i * 16,          (const char*)g_Qh + gQ + i * 16);
                cpa16(dQ + A_QL + i * 16,   (const char*)g_Ql + gQ + i * 16);
                cpa16(dKV + i * 16,         (const char*)g_Kh + gB + i * 16);
                cpa16(dKV + 9216 + i * 16,  (const char*)g_Kl + gB + i * 16);
                cpa16(dKV + 18432 + i * 16, (const char*)g_Vh + gB + i * 16);
            }
            CP_COMMIT();
        }
        CP_WAIT0();
        __syncthreads();

        uint32_t aqh[4][4], aql[4][4];
#pragma unroll
        for (int c = 0; c < 4; c++) {
            ldm_x4(sb + qBase + c * 32, aqh[c]);
            ldm_x4(sb + A_QL + qBase + c * 32, aql[c]);
        }

        float m0 = -1e30f, m1 = -1e30f;
        float O[8][4];
        float lacc[4];
#pragma unroll
        for (int j = 0; j < 8; j++)
#pragma unroll
            for (int i = 0; i < 4; i++) O[j][i] = 0.0f;
#pragma unroll
        for (int i = 0; i < 4; i++) lacc[i] = 0.0f;

        for (int kt = 0; kt < SEQ / 64; kt++) {
            const uint32_t kv = sb + A_STG0 + (uint32_t)(kt & 1) * A_STGSZ;

            if (kt + 1 < SEQ / 64) {
                const size_t gB = ((size_t)(b * SEQ + (kt + 1) * 64 + lr) * DMODEL + hoff) * 2 + lq * 64;
                const uint32_t d = sb + A_STG0 + (uint32_t)((kt + 1) & 1) * A_STGSZ + ldKV;
#pragma unroll
                for (int i = 0; i < 4; i++) {
                    cpa16(d + i * 16,         (const char*)g_Kh + gB + i * 16);
                    cpa16(d + 9216 + i * 16,  (const char*)g_Kl + gB + i * 16);
                    cpa16(d + 18432 + i * 16, (const char*)g_Vh + gB + i * 16);
                }
                CP_COMMIT();
            }

            // ---- S = Q K^T (raw), fp16 3-term, jj-pair reorder ----
            float S[8][4];
#pragma unroll
            for (int j = 0; j < 8; j++)
#pragma unroll
                for (int i = 0; i < 4; i++) S[j][i] = 0.0f;

#pragma unroll
            for (int c = 0; c < 4; c++) {
#pragma unroll
                for (int p = 0; p < 2; p++) {
                    uint32_t kh0[4], kh1[4], kl0[4], kl1[4];
                    ldm_x4(kv + kBase + (2 * p) * 2304 + c * 32, kh0);
                    ldm_x4(kv + kBase + (2 * p + 1) * 2304 + c * 32, kh1);
                    ldm_x4(kv + 9216 + kBase + (2 * p) * 2304 + c * 32, kl0);
                    ldm_x4(kv + 9216 + kBase + (2 * p + 1) * 2304 + c * 32, kl1);
                    mma_f16(S[4 * p],     aqh[c], kh0[0], kh0[1]);
                    mma_f16(S[4 * p + 1], aqh[c], kh0[2], kh0[3]);
                    mma_f16(S[4 * p + 2], aqh[c], kh1[0], kh1[1]);
                    mma_f16(S[4 * p + 3], aqh[c], kh1[2], kh1[3]);
                    mma_f16(S[4 * p],     aql[c], kh0[0], kh0[1]);
                    mma_f16(S[4 * p + 1], aql[c], kh0[2], kh0[3]);
                    mma_f16(S[4 * p + 2], aql[c], kh1[0], kh1[1]);
                    mma_f16(S[4 * p + 3], aql[c], kh1[2], kh1[3]);
                    mma_f16(S[4 * p],     aqh[c], kl0[0], kl0[1]);
                    mma_f16(S[4 * p + 1], aqh[c], kl0[2], kl0[3]);
                    mma_f16(S[4 * p + 2], aqh[c], kl1[0], kl1[1]);
                    mma_f16(S[4 * p + 3], aqh[c], kl1[2], kl1[3]);
                }
            }

            // ---- softmax ----
            float mx0 = -1e30f, mx1 = -1e30f;
#pragma unroll
            for (int j = 0; j < 8; j++) {
                mx0 = fmaxf(mx0, fmaxf(S[j][0], S[j][1]));
                mx1 = fmaxf(mx1, fmaxf(S[j][2], S[j][3]));
            }
            mx0 = fmaxf(mx0, __shfl_xor_sync(0xffffffffu, mx0, 1));
            mx0 = fmaxf(mx0, __shfl_xor_sync(0xffffffffu, mx0, 2));
            mx1 = fmaxf(mx1, __shfl_xor_sync(0xffffffffu, mx1, 1));
            mx1 = fmaxf(mx1, __shfl_xor_sync(0xffffffffu, mx1, 2));
            const float mn0 = fmaxf(m0, mx0), mn1 = fmaxf(m1, mx1);
            const float al0 = ex2((m0 - mn0) * CEXP);
            const float al1 = ex2((m1 - mn1) * CEXP);
            m0 = mn0; m1 = mn1;
            const float mc0 = m0 * CEXP;
            const float mc1 = m1 * CEXP;

            uint32_t P[8][2];
#pragma unroll
            for (int j = 0; j < 8; j++) {
                float x0 = fmaf(S[j][0], CEXP, -mc0);
                float x1 = fmaf(S[j][1], CEXP, -mc0);
                float x2 = fmaf(S[j][2], CEXP, -mc1);
                float x3 = fmaf(S[j][3], CEXP, -mc1);
                P[j][0] = h2ex2(pack_h2(x0, x1));
                P[j][1] = h2ex2(pack_h2(x2, x3));
            }

#pragma unroll
            for (int j = 0; j < 8; j++) {
                O[j][0] *= al0; O[j][1] *= al0;
                O[j][2] *= al1; O[j][3] *= al1;
            }
            lacc[0] *= al0; lacc[1] *= al0;
            lacc[2] *= al1; lacc[3] *= al1;

            // ---- O += P V ; l += P @ ones  (front-loaded V ldmatrix) ----
#pragma unroll
            for (int c = 0; c < 4; c++) {
                uint32_t ph[4];
                ph[0] = P[2 * c][0];
                ph[1] = P[2 * c][1];
                ph[2] = P[2 * c + 1][0];
                ph[3] = P[2 * c + 1][1];
                uint32_t v0[4], v1[4], v2[4], v3[4];
                ldm_x4t(kv + 18432 + vBase + c * 2304,      v0);
                ldm_x4t(kv + 18432 + vBase + c * 2304 + 32, v1);
                ldm_x4t(kv + 18432 + vBase + c * 2304 + 64, v2);
                ldm_x4t(kv + 18432 + vBase + c * 2304 + 96, v3);
                mma_f16(lacc, ph, ONE2, ONE2);
                mma_f16(O[0], ph, v0[0], v0[1]);
                mma_f16(O[1], ph, v0[2], v0[3]);
                mma_f16(O[2], ph, v1[0], v1[1]);
                mma_f16(O[3], ph, v1[2], v1[3]);
                mma_f16(O[4], ph, v2[0], v2[1]);
                mma_f16(O[5], ph, v2[2], v2[3]);
                mma_f16(O[6], ph, v3[0], v3[1]);
                mma_f16(O[7], ph, v3[2], v3[3]);
            }

            if (kt + 1 < SEQ / 64) {
                CP_WAIT0();
                __syncthreads();
            }
        }

        // ---- epilogue ----
        const float i0 = 1.0f / lacc[0];
        const float i1 = 1.0f / lacc[2];
        const size_t R0 = (size_t)(b * SEQ + q0 + 16 * w + g);
#pragma unroll
        for (int j = 0; j < 8; j++) {
            const int col = hoff + 8 * j + 2 * t4;
            *(float2*)&out[R0 * DMODEL + col] = make_float2(O[j][0] * i0, O[j][1] * i0);
            *(float2*)&out[(R0 + 8) * DMODEL + col] = make_float2(O[j][2] * i1, O[j][3] * i1);
        }
    }
}

// ===========================================================================
// kernel_launch
// ===========================================================================
extern "C" void kernel_launch(void* const* d_in, const int* in_sizes, int n_in,
                              void* d_out, int out_size)
{
    const float* q  = (const float*)d_in[0];
    const float* k  = (const float*)d_in[1];
    const float* v  = (const float*)d_in[2];
    const float* Wq = (const float*)d_in[3];
    const float* Wk = (const float*)d_in[4];
    const float* Wv = (const float*)d_in[5];
    float* out = (float*)d_out;

    ctr_reset<<<1, 1>>>();
    wt_convert<<<dim3(32, 32, 3), dim3(32, 8)>>>(Wq, Wk, Wv);
    in_convert<<<dim3(NELEM / 1024, 3), 256>>>(q, k, v);

    cudaFuncSetAttribute(proj_mma, cudaFuncAttributeMaxDynamicSharedMemorySize, PROJ_SMEM);
    proj_mma<<<PROJ_GRID, 256, PROJ_SMEM>>>();

    cudaFuncSetAttribute(attn_mma, cudaFuncAttributeMaxDynamicSharedMemorySize, ATTN_SMEM);
    attn_mma<<<ATTN_GRID, 128, ATTN_SMEM>>>(out);
}

// round 9
// speedup vs baseline: 1.0510x; 1.0510x over previous
#include <cuda_runtime.h>
#include <cuda_fp16.h>
#include <cstdint>

// Problem constants
#define BATCH   2
#define SEQ     2048
#define DMODEL  1024
#define NHEADS  16
#define HDIM    64
#define CEXP    92.33248261689366f   // SCALE(=64) * log2(e)
#define NELEM   (BATCH * SEQ * DMODEL)

// Scratch
__device__ __half g_WT_hi[3 * DMODEL * DMODEL];
__device__ __half g_WT_lo[3 * DMODEL * DMODEL];
__device__ __half g_Qh[NELEM];
__device__ __half g_Ql[NELEM];
__device__ __half g_Kh[NELEM];
__device__ __half g_Kl[NELEM];
__device__ __half g_Vh[NELEM];
__device__ unsigned g_ctr_attn;
__device__ unsigned g_ctr_proj;

// ===========================================================================
// Helpers (sm_80-era PTX only)
// ===========================================================================
__device__ __forceinline__ uint32_t smem_u32(const void* p) {
    uint32_t a;
    asm("{ .reg .u64 t; cvta.to.shared.u64 t, %1; cvt.u32.u64 %0, t; }" : "=r"(a) : "l"(p));
    return a;
}
__device__ __forceinline__ void ldm_x4(uint32_t addr, uint32_t* r) {
    asm volatile("ldmatrix.sync.aligned.m8n8.x4.shared.b16 {%0,%1,%2,%3}, [%4];"
                 : "=r"(r[0]), "=r"(r[1]), "=r"(r[2]), "=r"(r[3]) : "r"(addr));
}
__device__ __forceinline__ void ldm_x4t(uint32_t addr, uint32_t* r) {
    asm volatile("ldmatrix.sync.aligned.m8n8.x4.trans.shared.b16 {%0,%1,%2,%3}, [%4];"
                 : "=r"(r[0]), "=r"(r[1]), "=r"(r[2]), "=r"(r[3]) : "r"(addr));
}
__device__ __forceinline__ void mma_f16(float* c, const uint32_t* a, uint32_t b0, uint32_t b1) {
    asm volatile("mma.sync.aligned.m16n8k16.row.col.f32.f16.f16.f32 "
                 "{%0,%1,%2,%3}, {%4,%5,%6,%7}, {%8,%9}, {%0,%1,%2,%3};"
                 : "+f"(c[0]), "+f"(c[1]), "+f"(c[2]), "+f"(c[3])
                 : "r"(a[0]), "r"(a[1]), "r"(a[2]), "r"(a[3]), "r"(b0), "r"(b1));
}
__device__ __forceinline__ uint32_t pack_h2(float p0, float p1) {
    uint32_t h;
    asm("cvt.rn.f16x2.f32 %0, %1, %2;" : "=r"(h) : "f"(p1), "f"(p0));
    return h;
}
__device__ __forceinline__ void split2h(float p0, float p1, uint32_t& hi, uint32_t& lo) {
    uint32_t h = pack_h2(p0, p1);
    float f0, f1;
    asm("{.reg .b16 a,b; mov.b32 {a,b}, %2; cvt.f32.f16 %0, a; cvt.f32.f16 %1, b;}"
        : "=f"(f0), "=f"(f1) : "r"(h));
    hi = h;
    lo = pack_h2(p0 - f0, p1 - f1);
}
__device__ __forceinline__ float ex2(float x) {
    float r;
    asm("ex2.approx.f32 %0, %1;" : "=f"(r) : "f"(x));
    return r;
}
__device__ __forceinline__ uint32_t h2ex2(uint32_t x) {
    uint32_t r;
    asm("ex2.approx.f16x2 %0, %1;" : "=r"(r) : "r"(x));
    return r;
}
__device__ __forceinline__ void cpa16(uint32_t s, const void* g) {
    asm volatile("cp.async.cg.shared.global [%0], [%1], 16;" :: "r"(s), "l"(g));
}
#define CP_COMMIT() asm volatile("cp.async.commit_group;" ::: "memory")
#define CP_WAIT0()  asm volatile("cp.async.wait_group 0;" ::: "memory")

#define ONE2 0x3C003C00u   // fp16x2 {1.0, 1.0}

// ===========================================================================
// W transpose + split-fp16 convert (also resets work-steal counters)
// ===========================================================================
__global__ void wt_convert(const float* __restrict__ Wq, const float* __restrict__ Wk,
                           const float* __restrict__ Wv)
{
    if (blockIdx.x == 0 && blockIdx.y == 0 && blockIdx.z == 0 &&
        threadIdx.x == 0 && threadIdx.y == 0) {
        g_ctr_attn = 0u; g_ctr_proj = 0u;
    }
    __shared__ float tile[32][33];
    const float* W = (blockIdx.z == 0) ? Wq : (blockIdx.z == 1) ? Wk : Wv;
    const int tx = threadIdx.x, ty = threadIdx.y;
    const int k0 = blockIdx.y * 32, n0 = blockIdx.x * 32;
#pragma unroll
    for (int i = 0; i < 4; i++)
        tile[ty + i * 8][tx] = W[(size_t)(k0 + ty + i * 8) * DMODEL + n0 + tx];
    __syncthreads();
    const size_t base = (size_t)blockIdx.z * DMODEL * DMODEL;
#pragma unroll
    for (int i = 0; i < 4; i++) {
        const int n = n0 + ty + i * 8;
        const int k = k0 + tx;
        const float v = tile[tx][ty + i * 8];
        __half h = __float2half_rn(v);
        g_WT_hi[base + (size_t)n * DMODEL + k] = h;
        g_WT_lo[base + (size_t)n * DMODEL + k] = __float2half_rn(v - __half2float(h));
    }
}

// ===========================================================================
// Projection GEMM: fp16 mma, Q/K 3-term, V 1-term. A read as fp32 and
// register-split in-kernel (no converter pass). Work-stealing persistent,
// 2-stage pipeline (cp.async for B planes, LDG+STS for A planes).
// Stage (bytes): AH 0, AL 10240, BH 20480, BL 30720; stage size 40960.
// ===========================================================================
#define PSTG 40960
#define PROJ_SMEM (2 * PSTG)
#define PROJ_GRID 296
#define PROJ_UNITS 768

__device__ __forceinline__ void store_splitA(const float4* a, char* dst_stage,
                                             uint32_t ldB, int z)
{
    uint32_t hb[8], lb[8];
#pragma unroll
    for (int i = 0; i < 4; i++) {
        split2h(a[i].x, a[i].y, hb[2 * i], lb[2 * i]);
        split2h(a[i].z, a[i].w, hb[2 * i + 1], lb[2 * i + 1]);
    }
    char* dh = dst_stage + ldB;
    ((uint4*)dh)[0] = make_uint4(hb[0], hb[1], hb[2], hb[3]);
    ((uint4*)dh)[1] = make_uint4(hb[4], hb[5], hb[6], hb[7]);
    if (z < 2) {
        char* dl = dst_stage + 10240 + ldB;
        ((uint4*)dl)[0] = make_uint4(lb[0], lb[1], lb[2], lb[3]);
        ((uint4*)dl)[1] = make_uint4(lb[4], lb[5], lb[6], lb[7]);
    }
}

__global__ __launch_bounds__(256, 2) void proj_mma(const float* __restrict__ qi,
                                                   const float* __restrict__ ki,
                                                   const float* __restrict__ vi)
{
    extern __shared__ char smc[];
    const uint32_t sb = smem_u32(smc);
    int* su = (int*)(smc + 64);   // row-padding hole
    const int tid = threadIdx.x;
    const int lane = tid & 31;
    const int wid = tid >> 5;
    const int g = lane >> 2, t4 = lane & 3;
    const int wm = wid & 3, wn = wid >> 2;

    const uint32_t aBase = (uint32_t)(wm * 32 + (lane & 15)) * 80 + (lane >> 4) * 16;
    const uint32_t bBase = (uint32_t)(wn * 64 + (lane & 7) + ((lane >> 4) << 3)) * 80
                           + ((lane >> 3) & 1) * 16;
    const int lr = tid >> 1, lq = tid & 1;
    const uint32_t ldB = lr * 80 + lq * 32;

    while (true) {
        if (tid == 0) *su = (int)atomicAdd(&g_ctr_proj, 1u);
        __syncthreads();
        const int u = *su;
        if (u >= PROJ_UNITS) break;

        const int z = u >> 8;
        const int rem = u & 255;
        const int m0 = (rem >> 3) * 128;
        const int n0 = (rem & 7) * 128;

        const float* A;
        __half *Ch, *Cl;
        if (z == 0)      { A = qi; Ch = g_Qh; Cl = g_Ql; }
        else if (z == 1) { A = ki; Ch = g_Kh; Cl = g_Kl; }
        else             { A = vi; Ch = g_Vh; Cl = 0; }
        const size_t woff = (size_t)z * DMODEL * DMODEL;
        const char* BhG = (const char*)(g_WT_hi + woff);
        const char* BlG = (const char*)(g_WT_lo + woff);
        const size_t aRow = (size_t)(m0 + lr) * DMODEL;
        const size_t bRowB = (size_t)(n0 + lr) * DMODEL * 2;

        float c[2][8][4];
#pragma unroll
        for (int mb = 0; mb < 2; mb++)
#pragma unroll
            for (int j = 0; j < 8; j++)
#pragma unroll
                for (int i = 0; i < 4; i++) c[mb][j][i] = 0.0f;

        // prologue: A(0) via regs -> split -> stage0; B(0) via cp.async
        float4 a[4];
#pragma unroll
        for (int i = 0; i < 4; i++)
            a[i] = ((const float4*)(A + aRow + lq * 16))[i];
#pragma unroll
        for (int j = 0; j < 2; j++) {
            cpa16(sb + 20480 + ldB + j * 16, BhG + bRowB + lq * 32 + j * 16);
            if (z < 2)
                cpa16(sb + 30720 + ldB + j * 16, BlG + bRowB + lq * 32 + j * 16);
        }
        CP_COMMIT();
        store_splitA(a, smc, ldB, z);
        CP_WAIT0();
        __syncthreads();

        for (int kb = 0; kb < 32; kb++) {
            const uint32_t stg = (uint32_t)(kb & 1) * PSTG;
            const bool more = (kb + 1 < 32);
            if (more) {
                const int ko = (kb + 1) * 32;
#pragma unroll
                for (int i = 0; i < 4; i++)
                    a[i] = ((const float4*)(A + aRow + ko + lq * 16))[i];
                const uint32_t ns = sb + (uint32_t)((kb + 1) & 1) * PSTG;
#pragma unroll
                for (int j = 0; j < 2; j++) {
                    cpa16(ns + 20480 + ldB + j * 16, BhG + bRowB + ko * 2 + lq * 32 + j * 16);
                    if (z < 2)
                        cpa16(ns + 30720 + ldB + j * 16, BlG + bRowB + ko * 2 + lq * 32 + j * 16);
                }
                CP_COMMIT();
            }

            // ---- mma block (round-7 ordering) ----
#pragma unroll
            for (int c2 = 0; c2 < 2; c2++) {
                uint32_t ah[2][4], al[2][4];
#pragma unroll
                for (int mb = 0; mb < 2; mb++) {
                    ldm_x4(sb + stg + aBase + mb * 1280 + c2 * 32, ah[mb]);
                    if (z < 2)
                        ldm_x4(sb + stg + 10240 + aBase + mb * 1280 + c2 * 32, al[mb]);
                }
#pragma unroll
                for (int jj = 0; jj < 4; jj++) {
                    uint32_t r4[4];
                    ldm_x4(sb + stg + 20480 + bBase + jj * 1280 + c2 * 32, r4);
#pragma unroll
                    for (int mb = 0; mb < 2; mb++) {
                        mma_f16(c[mb][2 * jj], ah[mb], r4[0], r4[1]);
                        mma_f16(c[mb][2 * jj + 1], ah[mb], r4[2], r4[3]);
                        if (z < 2) {
                            mma_f16(c[mb][2 * jj], al[mb], r4[0], r4[1]);
                            mma_f16(c[mb][2 * jj + 1], al[mb], r4[2], r4[3]);
                        }
                    }
                }
                if (z < 2) {
#pragma unroll
                    for (int jj = 0; jj < 4; jj++) {
                        uint32_t r4[4];
                        ldm_x4(sb + stg + 30720 + bBase + jj * 1280 + c2 * 32, r4);
#pragma unroll
                        for (int mb = 0; mb < 2; mb++) {
                            mma_f16(c[mb][2 * jj], ah[mb], r4[0], r4[1]);
                            mma_f16(c[mb][2 * jj + 1], ah[mb], r4[2], r4[3]);
                        }
                    }
                }
            }

            if (more) {
                // split+store next A chunk into the other stage, then fence
                store_splitA(a, smc + (size_t)((kb + 1) & 1) * PSTG, ldB, z);
                CP_WAIT0();
                __syncthreads();
            }
        }

        // epilogue
#pragma unroll
        for (int mb = 0; mb < 2; mb++) {
#pragma unroll
            for (int j = 0; j < 8; j++) {
                const int R0 = m0 + wm * 32 + mb * 16 + g;
                const int col = n0 + wn * 64 + 8 * j + 2 * t4;
                if (z < 2) {
                    uint32_t hi, lo;
                    split2h(c[mb][j][0], c[mb][j][1], hi, lo);
                    *(uint32_t*)(Ch + (size_t)R0 * DMODEL + col) = hi;
                    *(uint32_t*)(Cl + (size_t)R0 * DMODEL + col) = lo;
                    split2h(c[mb][j][2], c[mb][j][3], hi, lo);
                    *(uint32_t*)(Ch + (size_t)(R0 + 8) * DMODEL + col) = hi;
                    *(uint32_t*)(Cl + (size_t)(R0 + 8) * DMODEL + col) = lo;
                } else {
                    *(uint32_t*)(Ch + (size_t)R0 * DMODEL + col) =
                        pack_h2(c[mb][j][0], c[mb][j][1]);
                    *(uint32_t*)(Ch + (size_t)(R0 + 8) * DMODEL + col) =
                        pack_h2(c[mb][j][2], c[mb][j][3]);
                }
            }
        }
    }
}

// ===========================================================================
// Flash attention (round-7 version): 128-thread CTAs, 64 Q-rows, 64-row K/V
// tiles, 3 CTAs/SM, work-stealing persistent, ONE sync per iteration.
// ===========================================================================
#define A_QL   9216
#define A_STG0 18432
#define A_STGSZ 27648
#define ATTN_SMEM 73728
#define ATTN_GRID 444
#define ATTN_UNITS 1024

__global__ __launch_bounds__(128, 3) void attn_mma(float* __restrict__ out)
{
    extern __shared__ char smc[];
    const uint32_t sb = smem_u32(smc);
    int* su = (int*)(smc + 128);
    const int tid = threadIdx.x;
    const int lane = tid & 31;
    const int w = tid >> 5;
    const int g = lane >> 2, t4 = lane & 3;
    const int lr = tid >> 1, lq = tid & 1;
    const uint32_t ldKV = lr * 144 + lq * 64;

    const uint32_t qBase = (uint32_t)(16 * w + (lane & 15)) * 144 + (lane >> 4) * 16;
    const uint32_t kBase = (uint32_t)((lane & 7) + ((lane >> 4) << 3)) * 144
                           + ((lane >> 3) & 1) * 16;
    const uint32_t vBase = (uint32_t)((lane & 7) + (((lane >> 3) & 1) << 3)) * 144
                           + (lane >> 4) * 16;

    while (true) {
        if (tid == 0) *su = (int)atomicAdd(&g_ctr_attn, 1u);
        __syncthreads();
        const int u = *su;
        if (u >= ATTN_UNITS) break;

        const int b = u >> 9;
        const int h = (u >> 5) & 15;
        const int q0 = (u & 31) * 64;
        const int hoff = h * HDIM;

        // prologue: Q (2 planes) + KV tile 0
        {
            const size_t gQ = ((size_t)(b * SEQ + q0 + lr) * DMODEL + hoff) * 2 + lq * 64;
            const size_t gB = ((size_t)(b * SEQ + lr) * DMODEL + hoff) * 2 + lq * 64;
            const uint32_t dQ = sb + ldKV;
            const uint32_t dKV = sb + A_STG0 + ldKV;
#pragma unroll
            for (int i = 0; i < 4; i++) {
                cpa16(dQ + i * 16,          (const char*)g_Qh + gQ + i * 16);
                cpa16(dQ + A_QL + i * 16,   (const char*)g_Ql + gQ + i * 16);
                cpa16(dKV + i * 16,         (const char*)g_Kh + gB + i * 16);
                cpa16(dKV + 9216 + i * 16,  (const char*)g_Kl + gB + i * 16);
                cpa16(dKV + 18432 + i * 16, (const char*)g_Vh + gB + i * 16);
            }
            CP_COMMIT();
        }
        CP_WAIT0();
        __syncthreads();

        uint32_t aqh[4][4], aql[4][4];
#pragma unroll
        for (int c = 0; c < 4; c++) {
            ldm_x4(sb + qBase + c * 32, aqh[c]);
            ldm_x4(sb + A_QL + qBase + c * 32, aql[c]);
        }

        float m0 = -1e30f, m1 = -1e30f;
        float O[8][4];
        float lacc[4];
#pragma unroll
        for (int j = 0; j < 8; j++)
#pragma unroll
            for (int i = 0; i < 4; i++) O[j][i] = 0.0f;
#pragma unroll
        for (int i = 0; i < 4; i++) lacc[i] = 0.0f;

        for (int kt = 0; kt < SEQ / 64; kt++) {
            const uint32_t kv = sb + A_STG0 + (uint32_t)(kt & 1) * A_STGSZ;

            if (kt + 1 < SEQ / 64) {
                const size_t gB = ((size_t)(b * SEQ + (kt + 1) * 64 + lr) * DMODEL + hoff) * 2 + lq * 64;
                const uint32_t d = sb + A_STG0 + (uint32_t)((kt + 1) & 1) * A_STGSZ + ldKV;
#pragma unroll
                for (int i = 0; i < 4; i++) {
                    cpa16(d + i * 16,         (const char*)g_Kh + gB + i * 16);
                    cpa16(d + 9216 + i * 16,  (const char*)g_Kl + gB + i * 16);
                    cpa16(d + 18432 + i * 16, (const char*)g_Vh + gB + i * 16);
                }
                CP_COMMIT();
            }

            // ---- S = Q K^T (raw), fp16 3-term ----
            float S[8][4];
#pragma unroll
            for (int j = 0; j < 8; j++)
#pragma unroll
                for (int i = 0; i < 4; i++) S[j][i] = 0.0f;

#pragma unroll
            for (int c = 0; c < 4; c++) {
#pragma unroll
                for (int jj = 0; jj < 4; jj++) {
                    uint32_t kh[4], kl[4];
                    ldm_x4(kv + kBase + jj * 2304 + c * 32, kh);
                    ldm_x4(kv + 9216 + kBase + jj * 2304 + c * 32, kl);
                    mma_f16(S[2 * jj], aqh[c], kh[0], kh[1]);
                    mma_f16(S[2 * jj + 1], aqh[c], kh[2], kh[3]);
                    mma_f16(S[2 * jj], aql[c], kh[0], kh[1]);
                    mma_f16(S[2 * jj + 1], aql[c], kh[2], kh[3]);
                    mma_f16(S[2 * jj], aqh[c], kl[0], kl[1]);
                    mma_f16(S[2 * jj + 1], aqh[c], kl[2], kl[3]);
                }
            }

            // ---- softmax: fp32 max-reduce, exp via ex2.f16x2 -> packed P ----
            float mx0 = -1e30f, mx1 = -1e30f;
#pragma unroll
            for (int j = 0; j < 8; j++) {
                mx0 = fmaxf(mx0, fmaxf(S[j][0], S[j][1]));
                mx1 = fmaxf(mx1, fmaxf(S[j][2], S[j][3]));
            }
            mx0 = fmaxf(mx0, __shfl_xor_sync(0xffffffffu, mx0, 1));
            mx0 = fmaxf(mx0, __shfl_xor_sync(0xffffffffu, mx0, 2));
            mx1 = fmaxf(mx1, __shfl_xor_sync(0xffffffffu, mx1, 1));
            mx1 = fmaxf(mx1, __shfl_xor_sync(0xffffffffu, mx1, 2));
            const float mn0 = fmaxf(m0, mx0), mn1 = fmaxf(m1, mx1);
            const float al0 = ex2((m0 - mn0) * CEXP);
            const float al1 = ex2((m1 - mn1) * CEXP);
            m0 = mn0; m1 = mn1;
            const float mc0 = m0 * CEXP;
            const float mc1 = m1 * CEXP;

            uint32_t P[8][2];
#pragma unroll
            for (int j = 0; j < 8; j++) {
                float x0 = fmaf(S[j][0], CEXP, -mc0);
                float x1 = fmaf(S[j][1], CEXP, -mc0);
                float x2 = fmaf(S[j][2], CEXP, -mc1);
                float x3 = fmaf(S[j][3], CEXP, -mc1);
                P[j][0] = h2ex2(pack_h2(x0, x1));
                P[j][1] = h2ex2(pack_h2(x2, x3));
            }

#pragma unroll
            for (int j = 0; j < 8; j++) {
                O[j][0] *= al0; O[j][1] *= al0;
                O[j][2] *= al1; O[j][3] *= al1;
            }
            lacc[0] *= al0; lacc[1] *= al0;
            lacc[2] *= al1; lacc[3] *= al1;

            // ---- O += P V ; l += P @ ones ----
#pragma unroll
            for (int c = 0; c < 4; c++) {
                uint32_t ph[4];
                ph[0] = P[2 * c][0];
                ph[1] = P[2 * c][1];
                ph[2] = P[2 * c + 1][0];
                ph[3] = P[2 * c + 1][1];
                mma_f16(lacc, ph, ONE2, ONE2);
#pragma unroll
                for (int jj = 0; jj < 4; jj++) {
                    uint32_t r4[4];
                    ldm_x4t(kv + 18432 + vBase + c * 2304 + jj * 32, r4);
                    mma_f16(O[2 * jj], ph, r4[0], r4[1]);
                    mma_f16(O[2 * jj + 1], ph, r4[2], r4[3]);
                }
            }

            if (kt + 1 < SEQ / 64) {
                CP_WAIT0();
                __syncthreads();
            }
        }

        // ---- epilogue ----
        const float i0 = 1.0f / lacc[0];
        const float i1 = 1.0f / lacc[2];
        const size_t R0 = (size_t)(b * SEQ + q0 + 16 * w + g);
#pragma unroll
        for (int j = 0; j < 8; j++) {
            const int col = hoff + 8 * j + 2 * t4;
            *(float2*)&out[R0 * DMODEL + col] = make_float2(O[j][0] * i0, O[j][1] * i0);
            *(float2*)&out[(R0 + 8) * DMODEL + col] = make_float2(O[j][2] * i1, O[j][3] * i1);
        }
    }
}

// ===========================================================================
// kernel_launch
// ===========================================================================
extern "C" void kernel_launch(void* const* d_in, const int* in_sizes, int n_in,
                              void* d_out, int out_size)
{
    const float* q  = (const float*)d_in[0];
    const float* k  = (const float*)d_in[1];
    const float* v  = (const float*)d_in[2];
    const float* Wq = (const float*)d_in[3];
    const float* Wk = (const float*)d_in[4];
    const float* Wv = (const float*)d_in[5];
    float* out = (float*)d_out;

    wt_convert<<<dim3(32, 32, 3), dim3(32, 8)>>>(Wq, Wk, Wv);

    cudaFuncSetAttribute(proj_mma, cudaFuncAttributeMaxDynamicSharedMemorySize, PROJ_SMEM);
    proj_mma<<<PROJ_GRID, 256, PROJ_SMEM>>>(q, k, v);

    cudaFuncSetAttribute(attn_mma, cudaFuncAttributeMaxDynamicSharedMemorySize, ATTN_SMEM);
    attn_mma<<<ATTN_GRID, 128, ATTN_SMEM>>>(out);
}